// round 3
// baseline (speedup 1.0000x reference)
#include <cuda_runtime.h>
#include <cstdint>

// Problem constants
#define NROWS   32768
#define NCODES  8192
#define DIM     256

// Tiling
#define BM      128      // rows per block
#define BN      128      // codes per chunk
#define BK      32       // k-slice
#define TM      8        // rows per thread
#define TN      8        // codes per thread
#define THREADS 256      // 16 x 16
#define PITCH   132      // BM + 4 pad (keeps float4 alignment, breaks stride-128 conflicts)

// Scratch: per-code squared norms
__device__ float g_esq[NCODES];

// ---------------------------------------------------------------------------
// Kernel 1: e_sq[k] = ||embed_k||^2   (one warp per code row)
// ---------------------------------------------------------------------------
__global__ void esq_kernel(const float* __restrict__ embed) {
    int warp = (blockIdx.x * blockDim.x + threadIdx.x) >> 5;
    int lane = threadIdx.x & 31;
    if (warp >= NCODES) return;
    const float* row = embed + (size_t)warp * DIM;
    float s = 0.f;
    #pragma unroll
    for (int d = lane; d < DIM; d += 32) { float v = row[d]; s = fmaf(v, v, s); }
    #pragma unroll
    for (int off = 16; off; off >>= 1) s += __shfl_down_sync(0xffffffffu, s, off);
    if (lane == 0) g_esq[warp] = s;
}

// ---------------------------------------------------------------------------
// Kernel 2: fused  (X @ E^T  -> argmin over codes -> gather -> write)
// One block owns BM=128 rows and streams all 8192 codes in BN=128 chunks.
// X tile kept transposed in SMEM for the whole block; E double-buffered.
// ---------------------------------------------------------------------------
__global__ void __launch_bounds__(THREADS, 1)
vq_kernel(const float* __restrict__ x,
          const float* __restrict__ embed,
          float* __restrict__ out) {
    extern __shared__ float smem[];
    float* Xs      = smem;                        // [DIM][PITCH]  (transposed X tile)
    float* Es      = Xs + DIM * PITCH;            // [2][BK][PITCH] (transposed E k-slices)
    float* esq_s   = Es + 2 * BK * PITCH;         // [BN]
    int*   rowidx  = (int*)(esq_s + BN);          // [BM]

    const int tid  = threadIdx.x;
    const int tx   = tid & 15;                    // code-tile coord
    const int ty   = tid >> 4;                    // row-tile coord
    const int row0 = blockIdx.x * BM;

    // ---- Load X tile transposed: Xs[d][r] = x[row0+r][d] (coalesced global reads)
    for (int idx = tid; idx < BM * DIM; idx += THREADS) {
        int r = idx >> 8;            // / DIM
        int d = idx & 255;           // % DIM
        Xs[d * PITCH + r] = x[(size_t)(row0 + r) * DIM + d];
    }

    float mv[TM];
    int   mi[TM];
    #pragma unroll
    for (int i = 0; i < TM; ++i) { mv[i] = __int_as_float(0x7f800000); mi[i] = 0x7fffffff; }

    const int kl = tid & 31;   // k-lane within a 32-wide slice (coalesced E reads)
    const int cl = tid >> 5;   // base code within slice load

    for (int chunk = 0; chunk < NCODES / BN; ++chunk) {
        const int c0 = chunk * BN;

        if (tid < BN) esq_s[tid] = g_esq[c0 + tid];

        float acc[TM][TN];
        #pragma unroll
        for (int i = 0; i < TM; ++i)
            #pragma unroll
            for (int j = 0; j < TN; ++j) acc[i][j] = 0.f;

        // Preload k-tile 0 into buffer 0: Es[k][c] = embed[c0+c][k]
        #pragma unroll
        for (int p = 0; p < 16; ++p) {
            int c = cl + p * 8;
            Es[kl * PITCH + c] = embed[(size_t)(c0 + c) * DIM + kl];
        }
        __syncthreads();

        int buf = 0;
        #pragma unroll 1
        for (int kt = 0; kt < DIM / BK; ++kt) {
            // Prefetch next k-tile into registers while computing
            float stage[16];
            if (kt + 1 < DIM / BK) {
                const int kk = (kt + 1) * BK;
                #pragma unroll
                for (int p = 0; p < 16; ++p)
                    stage[p] = embed[(size_t)(c0 + cl + p * 8) * DIM + kk + kl];
            }

            const float* XsB = Xs + kt * BK * PITCH;
            const float* EsB = Es + buf * BK * PITCH;

            #pragma unroll 8
            for (int k = 0; k < BK; ++k) {
                float4 a0 = *(const float4*)(XsB + k * PITCH + ty * TM);
                float4 a1 = *(const float4*)(XsB + k * PITCH + ty * TM + 4);
                float4 b0 = *(const float4*)(EsB + k * PITCH + tx * TN);
                float4 b1 = *(const float4*)(EsB + k * PITCH + tx * TN + 4);
                float a[TM] = {a0.x, a0.y, a0.z, a0.w, a1.x, a1.y, a1.z, a1.w};
                float b[TN] = {b0.x, b0.y, b0.z, b0.w, b1.x, b1.y, b1.z, b1.w};
                #pragma unroll
                for (int i = 0; i < TM; ++i)
                    #pragma unroll
                    for (int j = 0; j < TN; ++j)
                        acc[i][j] = fmaf(a[i], b[j], acc[i][j]);
            }

            // Commit prefetched tile to the other buffer
            if (kt + 1 < DIM / BK) {
                float* EsN = Es + (buf ^ 1) * BK * PITCH;
                #pragma unroll
                for (int p = 0; p < 16; ++p)
                    EsN[kl * PITCH + cl + p * 8] = stage[p];
            }
            __syncthreads();
            buf ^= 1;
        }

        // Score + running argmin.  dist = x^2 + (e^2 - 2*dot); x^2 is a per-row
        // constant so argmin ignores it. Strict '<' keeps first (lowest) index.
        #pragma unroll
        for (int j = 0; j < TN; ++j) {
            int   c  = c0 + tx * TN + j;
            float e2 = esq_s[tx * TN + j];
            #pragma unroll
            for (int i = 0; i < TM; ++i) {
                float s = fmaf(-2.f, acc[i][j], e2);
                if (s < mv[i]) { mv[i] = s; mi[i] = c; }
            }
        }
        __syncthreads();   // protect esq_s / Es before next chunk rewrites them
    }

    // ---- Reduce (min, idx) across the 16 tx-threads that share each row.
    // tid = ty*16 + tx -> those 16 threads are a contiguous half-warp.
    #pragma unroll
    for (int i = 0; i < TM; ++i) {
        float v  = mv[i];
        int   ii = mi[i];
        #pragma unroll
        for (int off = 8; off; off >>= 1) {
            float ov = __shfl_down_sync(0xffffffffu, v,  off, 16);
            int   oi = __shfl_down_sync(0xffffffffu, ii, off, 16);
            if (ov < v || (ov == v && oi < ii)) { v = ov; ii = oi; }
        }
        if (tx == 0) rowidx[ty * TM + i] = ii;
    }
    __syncthreads();

    // ---- Epilogue: quantize = (embed[idx] - x) + x  (straight-through), coalesced
    for (int idx = tid; idx < BM * DIM; idx += THREADS) {
        int r = idx >> 8;
        int d = idx & 255;
        int code = rowidx[r];
        float q  = embed[(size_t)code * DIM + d];
        float xv = x[(size_t)(row0 + r) * DIM + d];
        out[(size_t)(row0 + r) * DIM + d] = (q - xv) + xv;
    }
    if (tid < BM)
        out[(size_t)NROWS * DIM + row0 + tid] = (float)rowidx[tid];
}

// ---------------------------------------------------------------------------
extern "C" void kernel_launch(void* const* d_in, const int* in_sizes, int n_in,
                              void* d_out, int out_size) {
    const float* x     = (const float*)d_in[0];   // inputs_flatten [32768, 256]
    const float* embed = (const float*)d_in[1];   // embed          [8192, 256]
    float*       out   = (float*)d_out;           // quantize[N,256] ++ indices[N]

    const int smem_bytes = (DIM * PITCH + 2 * BK * PITCH + BN) * (int)sizeof(float)
                         + BM * (int)sizeof(int);   // = 169,984 B

    cudaFuncSetAttribute(vq_kernel, cudaFuncAttributeMaxDynamicSharedMemorySize,
                         smem_bytes);

    esq_kernel<<<NCODES * 32 / 256, 256>>>(embed);
    vq_kernel<<<NROWS / BM, THREADS, smem_bytes>>>(x, embed, out);
}

// round 6
// speedup vs baseline: 1.1801x; 1.1801x over previous
#include <cuda_runtime.h>
#include <cstdint>

// ---------------------------------------------------------------------------
// VQ codebook assignment, N=32768 rows, K=8192 codes, D=256 (fp32).
// Legacy tensor path (harness compiles plain sm_100 -> no tcgen05):
// mma.sync.m16n8k8.tf32 with 3-product fp32 split (Ah*Bh + Ah*Bl + Al*Bh),
// fused argmin, cp.async 3-stage E pipeline, gather epilogue.
// ---------------------------------------------------------------------------

#define NROWS   32768
#define NCODES  8192
#define DIM     256

#define BM      128                   // rows per CTA
#define BN      128                   // codes per chunk
#define NCHUNKS (NCODES / BN)         // 64
#define KCD     32                    // dims per pipeline stage
#define NKC     (DIM / KCD)           // 8
#define NSTG    3                     // cp.async stages
#define THREADS 256

#define XP 264                        // X smem pitch (floats): 256+8 -> 2-phase LDS.64
#define EP 40                         // E smem pitch (floats): 32+8

#define SM_X    0
#define SM_E    (BM * XP * 4)                     // 135168
#define SM_ESQ  (SM_E + NSTG * BM * EP * 4)       // 196608
#define SM_RED  (SM_ESQ + 512)                    // 197120
#define SM_IDX  (SM_RED + 4 * BM * 8)             // 201216
#define SMEM_TOTAL (SM_IDX + 512)                 // 201728

__device__ float g_esq[NCODES];

// ---------------- helpers ----------------
__device__ __forceinline__ uint32_t smem_u32(const void* p) {
    uint32_t a;
    asm("{ .reg .u64 t; cvta.to.shared.u64 t, %1; cvt.u32.u64 %0, t; }" : "=r"(a) : "l"(p));
    return a;
}
__device__ __forceinline__ void split_tf32(float v, uint32_t& h, uint32_t& l) {
    uint32_t hv = __float_as_uint(v) & 0xFFFFE000u;       // exact in tf32
    h = hv;
    l = __float_as_uint(v - __uint_as_float(hv));         // exact residual
}
__device__ __forceinline__ void mma_tf32(float* c, const uint32_t* a, const uint32_t* b) {
    asm volatile(
        "mma.sync.aligned.m16n8k8.row.col.f32.tf32.tf32.f32 "
        "{%0,%1,%2,%3}, {%4,%5,%6,%7}, {%8,%9}, {%0,%1,%2,%3};"
        : "+f"(c[0]), "+f"(c[1]), "+f"(c[2]), "+f"(c[3])
        : "r"(a[0]), "r"(a[1]), "r"(a[2]), "r"(a[3]), "r"(b[0]), "r"(b[1]));
}
__device__ __forceinline__ unsigned long long mk_key(float v, int idx) {
    uint32_t u = __float_as_uint(v);
    u ^= (u & 0x80000000u) ? 0xFFFFFFFFu : 0x80000000u;   // orderable float
    return ((unsigned long long)u << 32) | (uint32_t)idx; // ties -> lower idx wins
}
__device__ __forceinline__ unsigned long long umin64(unsigned long long a,
                                                     unsigned long long b) {
    return a < b ? a : b;
}

// Issue one E stage (128 codes x 32 dims fp32) via cp.async.cg (L2-cached).
__device__ __forceinline__ void issue_stage(const float* __restrict__ embed,
                                            uint32_t sbase, int s, int tid) {
    const int chunk = s >> 3, kc = s & 7, buf = s % NSTG;
    const int r = tid >> 1, h = tid & 1;
    const float* src = embed + (size_t)(chunk * BN + r) * DIM + kc * KCD + h * 16;
    uint32_t dst = sbase + SM_E + (uint32_t)(((buf * BM + r) * EP + h * 16) * 4);
    #pragma unroll
    for (int i = 0; i < 4; ++i)
        asm volatile("cp.async.cg.shared.global [%0], [%1], 16;"
                     :: "r"(dst + i * 16), "l"(src + i * 4) : "memory");
}

// ---------------------------------------------------------------------------
// Kernel 1: e_sq[k] = ||embed_k||^2
// ---------------------------------------------------------------------------
__global__ void esq_kernel(const float* __restrict__ embed) {
    int warp = (blockIdx.x * blockDim.x + threadIdx.x) >> 5;
    int lane = threadIdx.x & 31;
    if (warp >= NCODES) return;
    const float* row = embed + (size_t)warp * DIM;
    float s = 0.f;
    #pragma unroll
    for (int d = lane; d < DIM; d += 32) { float v = row[d]; s = fmaf(v, v, s); }
    #pragma unroll
    for (int off = 16; off; off >>= 1) s += __shfl_down_sync(0xffffffffu, s, off);
    if (lane == 0) g_esq[warp] = s;
}

// ---------------------------------------------------------------------------
// Kernel 2: split-tf32 mma.sync GEMM + fused argmin + gather
// ---------------------------------------------------------------------------
__global__ void __launch_bounds__(THREADS, 1)
vq_mma_kernel(const float* __restrict__ x,
              const float* __restrict__ embed,
              float* __restrict__ out) {
    extern __shared__ char smem[];
    float* Xs    = (float*)(smem + SM_X);
    float* Es    = (float*)(smem + SM_E);
    float* esq_s = (float*)(smem + SM_ESQ);
    unsigned long long* red = (unsigned long long*)(smem + SM_RED);
    int* rowidx  = (int*)(smem + SM_IDX);
    const uint32_t sbase = smem_u32(smem);

    const int tid  = threadIdx.x;
    const int lane = tid & 31;
    const int wid  = tid >> 5;
    const int wm   = wid & 1;            // 2 m-warp rows (64 rows each)
    const int wn   = wid >> 1;           // 4 n-warp cols (32 codes each)
    const int gq   = lane >> 2;          // fragment row/col group (0..7)
    const int q    = lane & 3;           // k-quad (0..3)
    const int row0 = blockIdx.x * BM;

    // prologue: 2 E stages in flight
    issue_stage(embed, sbase, 0, tid);
    asm volatile("cp.async.commit_group;" ::: "memory");
    issue_stage(embed, sbase, 1, tid);
    asm volatile("cp.async.commit_group;" ::: "memory");

    // X tile: 128 rows x 256 dims fp32, float4 coalesced
    #pragma unroll
    for (int i = 0; i < 32; ++i) {
        int idx = tid + i * THREADS;
        int r = idx >> 6, c4 = (idx & 63) << 2;
        *(float4*)(Xs + r * XP + c4) =
            *(const float4*)(x + (size_t)(row0 + r) * DIM + c4);
    }

    unsigned long long runkey = ~0ull;     // per-row running (dist,idx) key (tid<128)

    #pragma unroll 1
    for (int c = 0; c < NCHUNKS; ++c) {
        float acc[4][4][4];                // [m-frag][n-frag][c-reg]
        #pragma unroll
        for (int f = 0; f < 4; ++f)
            #pragma unroll
            for (int j = 0; j < 4; ++j)
                #pragma unroll
                for (int r = 0; r < 4; ++r) acc[f][j][r] = 0.f;

        #pragma unroll 1
        for (int kc = 0; kc < NKC; ++kc) {
            asm volatile("cp.async.wait_group 1;" ::: "memory");
            __syncthreads();
            if (kc == 0 && tid < BN) esq_s[tid] = g_esq[c * BN + tid];

            const int g = c * NKC + kc;
            const float* Eb = Es + (g % NSTG) * BM * EP;

            #pragma unroll
            for (int k8 = 0; k8 < 4; ++k8) {
                // k-slot permutation: slot q -> logical k 2q, slot q+4 -> 2q+1
                const int kcol = kc * KCD + k8 * 8 + 2 * q;   // X column
                const int ecol = k8 * 8 + 2 * q;              // E column (in stage)

                uint32_t ah[4][4], al[4][4];
                #pragma unroll
                for (int f = 0; f < 4; ++f) {
                    const int r = wm * 64 + f * 16 + gq;
                    float2 v0 = *(const float2*)(Xs + r * XP + kcol);
                    float2 v1 = *(const float2*)(Xs + (r + 8) * XP + kcol);
                    split_tf32(v0.x, ah[f][0], al[f][0]);   // a0: (r,   slot q)
                    split_tf32(v1.x, ah[f][1], al[f][1]);   // a1: (r+8, slot q)
                    split_tf32(v0.y, ah[f][2], al[f][2]);   // a2: (r,   slot q+4)
                    split_tf32(v1.y, ah[f][3], al[f][3]);   // a3: (r+8, slot q+4)
                }
                uint32_t bh[4][2], bl[4][2];
                #pragma unroll
                for (int j = 0; j < 4; ++j) {
                    const int n = wn * 32 + j * 8 + gq;
                    float2 w = *(const float2*)(Eb + n * EP + ecol);
                    split_tf32(w.x, bh[j][0], bl[j][0]);    // b0: slot q
                    split_tf32(w.y, bh[j][1], bl[j][1]);    // b1: slot q+4
                }
                #pragma unroll
                for (int f = 0; f < 4; ++f)
                    #pragma unroll
                    for (int j = 0; j < 4; ++j) {
                        mma_tf32(acc[f][j], ah[f], bh[j]);  // hi*hi
                        mma_tf32(acc[f][j], ah[f], bl[j]);  // hi*lo
                        mma_tf32(acc[f][j], al[f], bh[j]);  // lo*hi
                    }
            }

            if (g + 2 < NCHUNKS * NKC) issue_stage(embed, sbase, g + 2, tid);
            asm volatile("cp.async.commit_group;" ::: "memory");
        }

        // ---- fused argmin epilogue (dist = e^2 - 2*dot; x^2 is per-row const)
        #pragma unroll
        for (int f = 0; f < 4; ++f) {
            #pragma unroll
            for (int h = 0; h < 2; ++h) {      // h=0: rows +0 (c0,c1); h=1: +8 (c2,c3)
                unsigned long long best = ~0ull;
                #pragma unroll
                for (int j = 0; j < 4; ++j) {
                    const int nloc = wn * 32 + j * 8 + 2 * q;
                    const float2 e2 = *(const float2*)(esq_s + nloc);
                    float s0 = fmaf(-2.f, acc[f][j][2 * h + 0], e2.x);
                    float s1 = fmaf(-2.f, acc[f][j][2 * h + 1], e2.y);
                    best = umin64(best, mk_key(s0, c * BN + nloc));
                    best = umin64(best, mk_key(s1, c * BN + nloc + 1));
                }
                best = umin64(best, __shfl_xor_sync(0xffffffffu, best, 1));
                best = umin64(best, __shfl_xor_sync(0xffffffffu, best, 2));
                if (q == 0)
                    red[wn * BM + wm * 64 + f * 16 + h * 8 + gq] = best;
            }
        }
        __syncthreads();
        if (tid < BM) {
            unsigned long long k = red[tid];
            k = umin64(k, red[BM + tid]);
            k = umin64(k, red[2 * BM + tid]);
            k = umin64(k, red[3 * BM + tid]);
            runkey = umin64(runkey, k);
        }
    }

    // ---- indices + gather (x reread from smem; (q-x)+x matches ref rounding)
    if (tid < BM) rowidx[tid] = (int)(runkey & 0xffffffffull);
    __syncthreads();

    #pragma unroll 4
    for (int i2 = tid; i2 < BM * DIM; i2 += THREADS) {
        int r = i2 >> 8, d = i2 & 255;
        int code = rowidx[r];
        float qv = embed[(size_t)code * DIM + d];
        float xv = Xs[r * XP + d];
        out[(size_t)(row0 + r) * DIM + d] = (qv - xv) + xv;
    }
    if (tid < BM)
        out[(size_t)NROWS * DIM + row0 + tid] = (float)rowidx[tid];
}

// ---------------------------------------------------------------------------
extern "C" void kernel_launch(void* const* d_in, const int* in_sizes, int n_in,
                              void* d_out, int out_size) {
    const float* x     = (const float*)d_in[0];   // [32768, 256]
    const float* embed = (const float*)d_in[1];   // [8192, 256]
    float*       out   = (float*)d_out;

    cudaFuncSetAttribute(vq_mma_kernel, cudaFuncAttributeMaxDynamicSharedMemorySize,
                         SMEM_TOTAL);

    esq_kernel<<<NCODES * 32 / 256, 256>>>(embed);
    vq_mma_kernel<<<NROWS / BM, THREADS, SMEM_TOTAL>>>(x, embed, out);
}

// round 7
// speedup vs baseline: 2.1770x; 1.8447x over previous
#include <cuda_runtime.h>
#include <cstdint>

// ---------------------------------------------------------------------------
// VQ codebook assignment, N=32768 rows, K=8192 codes, D=256 (fp32).
// Phase 1: single-product tf32 mma.sync GEMM (raw fp32 fed, HW-truncated),
//          writes per-row minima of every 16-code group (approx distances).
// Phase 2: per row, exact fp32 rescore of all groups within margin of the
//          approx min (provably contains the true argmin), then gather.
// ---------------------------------------------------------------------------

#define NROWS   32768
#define NCODES  8192
#define DIM     256

#define BM      128                   // rows per CTA (phase 1)
#define BN      128                   // codes per chunk
#define NCHUNKS (NCODES / BN)         // 64
#define KCD     32                    // dims per pipeline stage
#define NKC     (DIM / KCD)           // 8
#define NSTG    3                     // cp.async stages
#define THREADS 256

#define NGRP    (NCODES / 16)         // 512 16-code groups
#define MARGIN  3.0f                  // >= 3x the worst-case 2*eps(dist) bound

#define XP 264                        // X smem pitch (floats)
#define EP 40                         // E smem pitch (floats)

#define SM_X    0
#define SM_E    (BM * XP * 4)                     // 135168
#define SM_ESQ  (SM_E + NSTG * BM * EP * 4)       // 196608
#define SMEM_TOTAL (SM_ESQ + 512)                 // 197120

__device__ float g_esq[NCODES];
__device__ float g_gmin[(size_t)NROWS * NGRP];    // 64 MB scratch (static)

// ---------------- helpers ----------------
__device__ __forceinline__ uint32_t smem_u32(const void* p) {
    uint32_t a;
    asm("{ .reg .u64 t; cvta.to.shared.u64 t, %1; cvt.u32.u64 %0, t; }" : "=r"(a) : "l"(p));
    return a;
}
__device__ __forceinline__ void mma_tf32(float* c, const uint32_t* a, const uint32_t* b) {
    asm volatile(
        "mma.sync.aligned.m16n8k8.row.col.f32.tf32.tf32.f32 "
        "{%0,%1,%2,%3}, {%4,%5,%6,%7}, {%8,%9}, {%0,%1,%2,%3};"
        : "+f"(c[0]), "+f"(c[1]), "+f"(c[2]), "+f"(c[3])
        : "r"(a[0]), "r"(a[1]), "r"(a[2]), "r"(a[3]), "r"(b[0]), "r"(b[1]));
}
__device__ __forceinline__ unsigned long long mk_key(float v, int idx) {
    uint32_t u = __float_as_uint(v);
    u ^= (u & 0x80000000u) ? 0xFFFFFFFFu : 0x80000000u;   // orderable float
    return ((unsigned long long)u << 32) | (uint32_t)idx; // ties -> lower idx
}
__device__ __forceinline__ unsigned long long umin64(unsigned long long a,
                                                     unsigned long long b) {
    return a < b ? a : b;
}

// one E stage (128 codes x 32 dims fp32) via cp.async.cg
__device__ __forceinline__ void issue_stage(const float* __restrict__ embed,
                                            uint32_t sbase, int s, int tid) {
    const int chunk = s >> 3, kc = s & 7, buf = s % NSTG;
    const int r = tid >> 1, h = tid & 1;
    const float* src = embed + (size_t)(chunk * BN + r) * DIM + kc * KCD + h * 16;
    uint32_t dst = sbase + SM_E + (uint32_t)(((buf * BM + r) * EP + h * 16) * 4);
    #pragma unroll
    for (int i = 0; i < 4; ++i)
        asm volatile("cp.async.cg.shared.global [%0], [%1], 16;"
                     :: "r"(dst + i * 16), "l"(src + i * 4) : "memory");
}

// ---------------------------------------------------------------------------
// Kernel 1: e_sq[k] = ||embed_k||^2
// ---------------------------------------------------------------------------
__global__ void esq_kernel(const float* __restrict__ embed) {
    int warp = (blockIdx.x * blockDim.x + threadIdx.x) >> 5;
    int lane = threadIdx.x & 31;
    if (warp >= NCODES) return;
    const float* row = embed + (size_t)warp * DIM;
    float s = 0.f;
    #pragma unroll
    for (int d = lane; d < DIM; d += 32) { float v = row[d]; s = fmaf(v, v, s); }
    #pragma unroll
    for (int off = 16; off; off >>= 1) s += __shfl_down_sync(0xffffffffu, s, off);
    if (lane == 0) g_esq[warp] = s;
}

// ---------------------------------------------------------------------------
// Kernel 2 (phase 1): tf32 GEMM + per-16-code-group approx-dist minima
// ---------------------------------------------------------------------------
__global__ void __launch_bounds__(THREADS, 1)
vq_p1_kernel(const float* __restrict__ x,
             const float* __restrict__ embed) {
    extern __shared__ char smem[];
    float* Xs    = (float*)(smem + SM_X);
    float* Es    = (float*)(smem + SM_E);
    float* esq_s = (float*)(smem + SM_ESQ);
    const uint32_t sbase = smem_u32(smem);

    const int tid  = threadIdx.x;
    const int lane = tid & 31;
    const int wid  = tid >> 5;
    const int wm   = wid & 1;            // 2 m-warp rows (64 rows each)
    const int wn   = wid >> 1;           // 4 n-warp cols (32 codes each)
    const int gq   = lane >> 2;          // fragment group (0..7)
    const int q    = lane & 3;           // k-quad (0..3)
    const int row0 = blockIdx.x * BM;

    issue_stage(embed, sbase, 0, tid);
    asm volatile("cp.async.commit_group;" ::: "memory");
    issue_stage(embed, sbase, 1, tid);
    asm volatile("cp.async.commit_group;" ::: "memory");

    // X tile: 128 rows x 256 dims fp32
    #pragma unroll
    for (int i = 0; i < 32; ++i) {
        int idx = tid + i * THREADS;
        int r = idx >> 6, c4 = (idx & 63) << 2;
        *(float4*)(Xs + r * XP + c4) =
            *(const float4*)(x + (size_t)(row0 + r) * DIM + c4);
    }

    #pragma unroll 1
    for (int c = 0; c < NCHUNKS; ++c) {
        float acc[4][4][4];
        #pragma unroll
        for (int f = 0; f < 4; ++f)
            #pragma unroll
            for (int j = 0; j < 4; ++j)
                #pragma unroll
                for (int r = 0; r < 4; ++r) acc[f][j][r] = 0.f;

        #pragma unroll 1
        for (int kc = 0; kc < NKC; ++kc) {
            asm volatile("cp.async.wait_group 1;" ::: "memory");
            __syncthreads();
            if (kc == 0 && tid < BN) esq_s[tid] = g_esq[c * BN + tid];

            const int g = c * NKC + kc;
            const float* Eb = Es + (g % NSTG) * BM * EP;

            #pragma unroll
            for (int k8 = 0; k8 < 4; ++k8) {
                // k-slot permutation: slot q <- logical 2q, slot q+4 <- 2q+1
                const int kcol = kc * KCD + k8 * 8 + 2 * q;
                const int ecol = k8 * 8 + 2 * q;

                uint32_t a[4][4];
                #pragma unroll
                for (int f = 0; f < 4; ++f) {
                    const int r = wm * 64 + f * 16 + gq;
                    float2 v0 = *(const float2*)(Xs + r * XP + kcol);
                    float2 v1 = *(const float2*)(Xs + (r + 8) * XP + kcol);
                    a[f][0] = __float_as_uint(v0.x);   // (r,   slot q)
                    a[f][1] = __float_as_uint(v1.x);   // (r+8, slot q)
                    a[f][2] = __float_as_uint(v0.y);   // (r,   slot q+4)
                    a[f][3] = __float_as_uint(v1.y);   // (r+8, slot q+4)
                }
                uint32_t b[4][2];
                #pragma unroll
                for (int j = 0; j < 4; ++j) {
                    const int n = wn * 32 + j * 8 + gq;
                    float2 w = *(const float2*)(Eb + n * EP + ecol);
                    b[j][0] = __float_as_uint(w.x);
                    b[j][1] = __float_as_uint(w.y);
                }
                #pragma unroll
                for (int f = 0; f < 4; ++f)
                    #pragma unroll
                    for (int j = 0; j < 4; ++j)
                        mma_tf32(acc[f][j], a[f], b[j]);
            }

            if (g + 2 < NCHUNKS * NKC) issue_stage(embed, sbase, g + 2, tid);
            asm volatile("cp.async.commit_group;" ::: "memory");
        }

        // ---- epilogue: per-row minima of the two 16-code groups this warp
        // covers (d = e^2 - 2*dot; per-row x^2 constant irrelevant for argmin)
        #pragma unroll
        for (int f = 0; f < 4; ++f) {
            #pragma unroll
            for (int h = 0; h < 2; ++h) {
                float m[2];
                #pragma unroll
                for (int gg = 0; gg < 2; ++gg) {
                    float mm = __int_as_float(0x7f800000);
                    #pragma unroll
                    for (int jj = 0; jj < 2; ++jj) {
                        const int j = gg * 2 + jj;
                        const int nloc = wn * 32 + j * 8 + 2 * q;
                        const float2 e2 = *(const float2*)(esq_s + nloc);
                        float d0 = fmaf(-2.f, acc[f][j][2 * h + 0], e2.x);
                        float d1 = fmaf(-2.f, acc[f][j][2 * h + 1], e2.y);
                        mm = fminf(mm, fminf(d0, d1));
                    }
                    mm = fminf(mm, __shfl_xor_sync(0xffffffffu, mm, 1));
                    mm = fminf(mm, __shfl_xor_sync(0xffffffffu, mm, 2));
                    m[gg] = mm;
                }
                if (q == 0) {
                    const int row = row0 + wm * 64 + f * 16 + h * 8 + gq;
                    float2 st = make_float2(m[0], m[1]);
                    *(float2*)(g_gmin + (size_t)row * NGRP + c * 8 + wn * 2) = st;
                }
            }
        }
    }
}

// ---------------------------------------------------------------------------
// Kernel 3 (phase 2): exact fp32 rescore of candidate groups + gather.
// One warp per row; block = 8 warps.
// ---------------------------------------------------------------------------
__global__ void __launch_bounds__(256, 1)
vq_p2_kernel(const float* __restrict__ x,
             const float* __restrict__ embed,
             float* __restrict__ out) {
    __shared__ float xs[8][DIM];          // 8 KB
    __shared__ float gm[8][NGRP];         // 16 KB

    const int lane = threadIdx.x & 31;
    const int w    = threadIdx.x >> 5;
    const int row  = blockIdx.x * 8 + w;

    // x row -> smem (64 float4)
    #pragma unroll
    for (int t = lane; t < 64; t += 32)
        *(float4*)(xs[w] + t * 4) = *(const float4*)(x + (size_t)row * DIM + t * 4);

    // group minima -> smem, tracking running min
    float mn = __int_as_float(0x7f800000);
    const float* gsrc = g_gmin + (size_t)row * NGRP;
    #pragma unroll
    for (int t = lane; t < NGRP / 4; t += 32) {
        float4 v = *(const float4*)(gsrc + t * 4);
        *(float4*)(gm[w] + t * 4) = v;
        mn = fminf(mn, fminf(fminf(v.x, v.y), fminf(v.z, v.w)));
    }
    #pragma unroll
    for (int off = 16; off; off >>= 1)
        mn = fminf(mn, __shfl_xor_sync(0xffffffffu, mn, off));
    const float thr = mn + MARGIN;
    __syncwarp();

    unsigned long long best = ~0ull;
    const int code_off = lane >> 1;       // 16 codes, 2 lanes each
    const int half     = lane & 1;        // 128-dim half per lane
    const float* xh = xs[w] + half * 128;

    #pragma unroll 1
    for (int t = 0; t < NGRP / 4; ++t) {  // 4 groups per iter (uniform branch)
        float4 gv = *(const float4*)(gm[w] + t * 4);
        float m4 = fminf(fminf(gv.x, gv.y), fminf(gv.z, gv.w));
        if (m4 > thr) continue;
        float ga[4] = {gv.x, gv.y, gv.z, gv.w};
        #pragma unroll
        for (int e = 0; e < 4; ++e) {
            if (ga[e] > thr) continue;
            const int G = t * 4 + e;
            const int code = G * 16 + code_off;
            const float* er = embed + (size_t)code * DIM + half * 128;
            float dot = 0.f;
            #pragma unroll
            for (int k = 0; k < 32; ++k) {
                float4 ev = *(const float4*)(er + k * 4);
                float4 xv = *(const float4*)(xh + k * 4);
                dot = fmaf(ev.x, xv.x, dot); dot = fmaf(ev.y, xv.y, dot);
                dot = fmaf(ev.z, xv.z, dot); dot = fmaf(ev.w, xv.w, dot);
            }
            dot += __shfl_xor_sync(0xffffffffu, dot, 1);      // both halves
            float d = fmaf(-2.f, dot, g_esq[code]);
            unsigned long long key = mk_key(d, code);
            #pragma unroll
            for (int off = 2; off < 32; off <<= 1)
                key = umin64(key, __shfl_xor_sync(0xffffffffu, key, off));
            key = umin64(key, __shfl_xor_sync(0xffffffffu, key, 1));
            best = umin64(best, key);
        }
    }

    const int bidx = (int)(best & 0xffffffffull);
    // gather: out = (q - x) + x  (reference rounding), coalesced
    #pragma unroll
    for (int t = lane; t < 64; t += 32) {
        float4 qv = *(const float4*)(embed + (size_t)bidx * DIM + t * 4);
        float4 xv = *(const float4*)(xs[w] + t * 4);
        float4 o;
        o.x = (qv.x - xv.x) + xv.x; o.y = (qv.y - xv.y) + xv.y;
        o.z = (qv.z - xv.z) + xv.z; o.w = (qv.w - xv.w) + xv.w;
        *(float4*)(out + (size_t)row * DIM + t * 4) = o;
    }
    if (lane == 0)
        out[(size_t)NROWS * DIM + row] = (float)bidx;
}

// ---------------------------------------------------------------------------
extern "C" void kernel_launch(void* const* d_in, const int* in_sizes, int n_in,
                              void* d_out, int out_size) {
    const float* x     = (const float*)d_in[0];   // [32768, 256]
    const float* embed = (const float*)d_in[1];   // [8192, 256]
    float*       out   = (float*)d_out;

    cudaFuncSetAttribute(vq_p1_kernel, cudaFuncAttributeMaxDynamicSharedMemorySize,
                         SMEM_TOTAL);

    esq_kernel<<<NCODES * 32 / 256, 256>>>(embed);
    vq_p1_kernel<<<NROWS / BM, THREADS, SMEM_TOTAL>>>(x, embed);
    vq_p2_kernel<<<NROWS / 8, 256>>>(x, embed, out);
}

// round 9
// speedup vs baseline: 3.3814x; 1.5533x over previous
#include <cuda_runtime.h>
#include <cuda_bf16.h>
#include <cstdint>

// ---------------------------------------------------------------------------
// VQ codebook assignment, N=32768 rows, K=8192 codes, D=256 (fp32).
// Phase 0: convert X,E to bf16 scratch; exact fp32 norms (e_sq, ||x||, max||e||).
// Phase 1: bf16 m16n8k16 mma.sync GEMM (ldmatrix-fed), per-16-code-group
//          approx-dist minima -> 64 MB scratch.
// Phase 2: per row, exact fp32 rescore of groups within a runtime-certified
//          margin (provably contains the true argmin), then gather.
// R9 fix vs R8: B fragments use NON-trans ldmatrix (E smem is n-row-major with
// k contiguous; non-trans yields the consecutive-k-at-fixed-n B fragment).
// ---------------------------------------------------------------------------

#define NROWS   32768
#define NCODES  8192
#define DIM     256

#define BM      128                   // rows per CTA (phase 1)
#define BN      128                   // codes per chunk
#define NCHUNKS (NCODES / BN)         // 64
#define NKC     8                     // 32-dim stages per chunk
#define NSTG    3
#define THREADS 256
#define NGRP    (NCODES / 16)         // 512

#define XPB     528                   // X smem row pitch bytes (264 bf16)
#define EPB     80                    // E smem row pitch bytes (40 bf16)
#define ESTG    (BM * EPB)            // 10240 per stage

#define SM_X    0
#define SM_E    (BM * XPB)                        // 67584
#define SM_ESQ  (SM_E + NSTG * ESTG)              // 98304
#define SMEM_TOTAL (SM_ESQ + 512 + 256)           // 99072

__device__ float          g_esq[NCODES];
__device__ float          g_xnorm[NROWS];
__device__ unsigned int   g_emax2b;               // max ||e||^2 (ordered bits)
__device__ __nv_bfloat16  g_xbf[(size_t)NROWS * DIM];    // 16 MB
__device__ __nv_bfloat16  g_ebf[(size_t)NCODES * DIM];   // 4 MB
__device__ float          g_gmin[(size_t)NROWS * NGRP];  // 64 MB

// ---------------- helpers ----------------
__device__ __forceinline__ uint32_t smem_u32(const void* p) {
    uint32_t a;
    asm("{ .reg .u64 t; cvta.to.shared.u64 t, %1; cvt.u32.u64 %0, t; }" : "=r"(a) : "l"(p));
    return a;
}
__device__ __forceinline__ uint32_t bf2(float lo, float hi) {   // pack (lo,hi)
    uint32_t r;
    asm("cvt.rn.bf16x2.f32 %0, %1, %2;" : "=r"(r) : "f"(hi), "f"(lo));
    return r;
}
__device__ __forceinline__ void mma_bf16(float* c, const uint32_t* a, const uint32_t* b) {
    asm volatile(
        "mma.sync.aligned.m16n8k16.row.col.f32.bf16.bf16.f32 "
        "{%0,%1,%2,%3}, {%4,%5,%6,%7}, {%8,%9}, {%0,%1,%2,%3};"
        : "+f"(c[0]), "+f"(c[1]), "+f"(c[2]), "+f"(c[3])
        : "r"(a[0]), "r"(a[1]), "r"(a[2]), "r"(a[3]), "r"(b[0]), "r"(b[1]));
}
__device__ __forceinline__ void ldsm_x4(uint32_t* r, uint32_t addr) {
    asm volatile("ldmatrix.sync.aligned.m8n8.x4.shared.b16 {%0,%1,%2,%3}, [%4];"
                 : "=r"(r[0]), "=r"(r[1]), "=r"(r[2]), "=r"(r[3]) : "r"(addr));
}
__device__ __forceinline__ unsigned long long mk_key(float v, int idx) {
    uint32_t u = __float_as_uint(v);
    u ^= (u & 0x80000000u) ? 0xFFFFFFFFu : 0x80000000u;
    return ((unsigned long long)u << 32) | (uint32_t)idx;
}
__device__ __forceinline__ unsigned long long umin64(unsigned long long a,
                                                     unsigned long long b) {
    return a < b ? a : b;
}

// one E stage: 128 codes x 32 dims bf16 (64 B/row) via cp.async
__device__ __forceinline__ void issue_stage(uint32_t sbase, int s, int tid) {
    const int chunk = s >> 3, kc = s & 7, buf = s % NSTG;
    const int r = tid >> 1, h = tid & 1;
    const __nv_bfloat16* src = g_ebf + (size_t)(chunk * BN + r) * DIM + kc * 32 + h * 16;
    uint32_t dst = sbase + SM_E + (uint32_t)(buf * ESTG + r * EPB + h * 32);
    asm volatile("cp.async.cg.shared.global [%0], [%1], 16;" :: "r"(dst),      "l"(src)     : "memory");
    asm volatile("cp.async.cg.shared.global [%0], [%1], 16;" :: "r"(dst + 16), "l"(src + 8) : "memory");
}

// ---------------------------------------------------------------------------
// Phase 0a: convert X -> bf16, compute ||x|| (one warp per row)
// ---------------------------------------------------------------------------
__global__ void conv_x_kernel(const float* __restrict__ x) {
    const int row  = blockIdx.x * 8 + (threadIdx.x >> 5);
    const int lane = threadIdx.x & 31;
    float s = 0.f;
    #pragma unroll
    for (int i = 0; i < 2; ++i) {
        const int off = i * 128 + lane * 4;
        float4 v = *(const float4*)(x + (size_t)row * DIM + off);
        s = fmaf(v.x, v.x, s); s = fmaf(v.y, v.y, s);
        s = fmaf(v.z, v.z, s); s = fmaf(v.w, v.w, s);
        uint2 p = make_uint2(bf2(v.x, v.y), bf2(v.z, v.w));
        *(uint2*)(g_xbf + (size_t)row * DIM + off) = p;
    }
    #pragma unroll
    for (int o = 16; o; o >>= 1) s += __shfl_xor_sync(0xffffffffu, s, o);
    if (lane == 0) g_xnorm[row] = sqrtf(s);
}

// ---------------------------------------------------------------------------
// Phase 0b: convert E -> bf16, e_sq, max ||e||^2 (one warp per row)
// ---------------------------------------------------------------------------
__global__ void conv_e_kernel(const float* __restrict__ embed) {
    const int row  = blockIdx.x * 8 + (threadIdx.x >> 5);
    const int lane = threadIdx.x & 31;
    float s = 0.f;
    #pragma unroll
    for (int i = 0; i < 2; ++i) {
        const int off = i * 128 + lane * 4;
        float4 v = *(const float4*)(embed + (size_t)row * DIM + off);
        s = fmaf(v.x, v.x, s); s = fmaf(v.y, v.y, s);
        s = fmaf(v.z, v.z, s); s = fmaf(v.w, v.w, s);
        uint2 p = make_uint2(bf2(v.x, v.y), bf2(v.z, v.w));
        *(uint2*)(g_ebf + (size_t)row * DIM + off) = p;
    }
    #pragma unroll
    for (int o = 16; o; o >>= 1) s += __shfl_xor_sync(0xffffffffu, s, o);
    if (lane == 0) {
        g_esq[row] = s;
        atomicMax(&g_emax2b, __float_as_uint(s));   // positive: bit order = value order
    }
}

// ---------------------------------------------------------------------------
// Phase 1: bf16 GEMM + per-16-code-group approx-dist minima
// ---------------------------------------------------------------------------
__global__ void __launch_bounds__(THREADS, 2)
vq_p1_kernel(void) {
    extern __shared__ char smem[];
    float* esq_s = (float*)(smem + SM_ESQ);
    const uint32_t sbase = smem_u32(smem);

    const int tid  = threadIdx.x;
    const int lane = tid & 31;
    const int wid  = tid >> 5;
    const int wm   = wid & 1;                 // 64-row half
    const int wn   = wid >> 1;                // 32-code quarter
    const int gq   = lane >> 2;
    const int q    = lane & 3;
    const int row0 = blockIdx.x * BM;

    issue_stage(sbase, 0, tid);
    asm volatile("cp.async.commit_group;" ::: "memory");
    issue_stage(sbase, 1, tid);
    asm volatile("cp.async.commit_group;" ::: "memory");

    // X tile: 128 rows x 256 bf16, pitch 528 B (LDSM conflict-free)
    #pragma unroll
    for (int i = 0; i < 16; ++i) {
        int idx = tid + i * THREADS;          // 0..4095 16B chunks
        int r = idx >> 5, o = idx & 31;
        *(uint4*)(smem + SM_X + r * XPB + o * 16) =
            *(const uint4*)(g_xbf + (size_t)(row0 + r) * DIM + o * 8);
    }

    // ldmatrix lane->address mapping (x4 = four 8x8 matrices)
    const int t = lane >> 3;
    // A: m0=(rows0-7,k0-7) m1=(rows8-15,k0-7) m2=(rows0-7,k8-15) m3=(rows8-15,k8-15)
    const uint32_t a_rowsel = (uint32_t)((t & 1) * 8 + (lane & 7));
    const uint32_t a_koff   = (uint32_t)((t >> 1) * 16);             // bytes
    uint32_t abase[4];
    #pragma unroll
    for (int f = 0; f < 4; ++f)
        abase[f] = sbase + SM_X + (wm * 64 + f * 16 + a_rowsel) * XPB + a_koff;
    // B: m0=(n0-7,k0-7) m1=(n0-7,k8-15) m2=(n8-15,k0-7) m3=(n8-15,k8-15)
    const uint32_t b_nsel = (uint32_t)(((lane >> 4) & 1) * 8 + (lane & 7));
    const uint32_t b_koff = (uint32_t)(((lane >> 3) & 1) * 16);      // bytes
    uint32_t bbase[2];
    #pragma unroll
    for (int jp = 0; jp < 2; ++jp)
        bbase[jp] = sbase + SM_E + (wn * 32 + jp * 16 + b_nsel) * EPB + b_koff;

    #pragma unroll 1
    for (int c = 0; c < NCHUNKS; ++c) {
        float acc[4][4][4];
        #pragma unroll
        for (int f = 0; f < 4; ++f)
            #pragma unroll
            for (int j = 0; j < 4; ++j)
                #pragma unroll
                for (int r = 0; r < 4; ++r) acc[f][j][r] = 0.f;

        #pragma unroll 1
        for (int kc = 0; kc < NKC; ++kc) {
            asm volatile("cp.async.wait_group 1;" ::: "memory");
            __syncthreads();
            if (kc == 0 && tid < BN) esq_s[tid] = g_esq[c * BN + tid];

            const int g = c * NKC + kc;
            const uint32_t ebuf = (uint32_t)((g % NSTG) * ESTG);

            #pragma unroll
            for (int s = 0; s < 2; ++s) {     // two k16 steps per 32-dim stage
                const uint32_t ak = (uint32_t)((kc * 32 + s * 16) * 2);
                const uint32_t bk = (uint32_t)(s * 32);
                uint32_t a[4][4], b[4][2];
                #pragma unroll
                for (int f = 0; f < 4; ++f) ldsm_x4(a[f], abase[f] + ak);
                #pragma unroll
                for (int jp = 0; jp < 2; ++jp) {
                    uint32_t rr[4];
                    ldsm_x4(rr, bbase[jp] + ebuf + bk);          // NON-trans (fix)
                    b[jp * 2][0]     = rr[0];  // (n0-7, k0-7)
                    b[jp * 2][1]     = rr[1];  // (n0-7, k8-15)
                    b[jp * 2 + 1][0] = rr[2];  // (n8-15, k0-7)
                    b[jp * 2 + 1][1] = rr[3];  // (n8-15, k8-15)
                }
                #pragma unroll
                for (int f = 0; f < 4; ++f)
                    #pragma unroll
                    for (int j = 0; j < 4; ++j)
                        mma_bf16(acc[f][j], a[f], b[j]);
            }

            if (g + 2 < NCHUNKS * NKC) issue_stage(sbase, g + 2, tid);
            asm volatile("cp.async.commit_group;" ::: "memory");
        }

        // ---- per-row minima of the 2 16-code groups this warp covers
        #pragma unroll
        for (int f = 0; f < 4; ++f) {
            #pragma unroll
            for (int h = 0; h < 2; ++h) {
                float m[2];
                #pragma unroll
                for (int gg = 0; gg < 2; ++gg) {
                    float mm = __int_as_float(0x7f800000);
                    #pragma unroll
                    for (int jj = 0; jj < 2; ++jj) {
                        const int j = gg * 2 + jj;
                        const int nloc = wn * 32 + j * 8 + 2 * q;
                        const float2 e2 = *(const float2*)(esq_s + nloc);
                        float d0 = fmaf(-2.f, acc[f][j][2 * h + 0], e2.x);
                        float d1 = fmaf(-2.f, acc[f][j][2 * h + 1], e2.y);
                        mm = fminf(mm, fminf(d0, d1));
                    }
                    mm = fminf(mm, __shfl_xor_sync(0xffffffffu, mm, 1));
                    mm = fminf(mm, __shfl_xor_sync(0xffffffffu, mm, 2));
                    m[gg] = mm;
                }
                if (q == 0) {
                    const int row = row0 + wm * 64 + f * 16 + h * 8 + gq;
                    *(float2*)(g_gmin + (size_t)row * NGRP + c * 8 + wn * 2) =
                        make_float2(m[0], m[1]);
                }
            }
        }
    }
}

// ---------------------------------------------------------------------------
// Phase 2: exact fp32 rescore of candidate groups + gather (1 warp/row)
// ---------------------------------------------------------------------------
__global__ void __launch_bounds__(256, 1)
vq_p2_kernel(const float* __restrict__ x,
             const float* __restrict__ embed,
             float* __restrict__ out) {
    __shared__ float xs[8][DIM];
    __shared__ float gm[8][NGRP];

    const int lane = threadIdx.x & 31;
    const int w    = threadIdx.x >> 5;
    const int row  = blockIdx.x * 8 + w;

    #pragma unroll
    for (int t = lane; t < 64; t += 32)
        *(float4*)(xs[w] + t * 4) = *(const float4*)(x + (size_t)row * DIM + t * 4);

    float mn = __int_as_float(0x7f800000);
    const float* gsrc = g_gmin + (size_t)row * NGRP;
    #pragma unroll
    for (int t = lane; t < NGRP / 4; t += 32) {
        float4 v = *(const float4*)(gsrc + t * 4);
        *(float4*)(gm[w] + t * 4) = v;
        mn = fminf(mn, fminf(fminf(v.x, v.y), fminf(v.z, v.w)));
    }
    #pragma unroll
    for (int off = 16; off; off >>= 1)
        mn = fminf(mn, __shfl_xor_sync(0xffffffffu, mn, off));

    // certified margin: dist err <= 2 * 2^-7 * ||x|| * ||e||max each side
    const float emax = sqrtf(__uint_as_float(g_emax2b));
    const float thr  = mn + fmaf(0.033f, g_xnorm[row] * emax, 0.1f);
    __syncwarp();

    unsigned long long best = ~0ull;
    const int code_off = lane >> 1;
    const int half     = lane & 1;
    const float* xh = xs[w] + half * 128;

    #pragma unroll 1
    for (int t = 0; t < NGRP / 4; ++t) {
        float4 gv = *(const float4*)(gm[w] + t * 4);
        float m4 = fminf(fminf(gv.x, gv.y), fminf(gv.z, gv.w));
        if (m4 > thr) continue;
        float ga[4] = {gv.x, gv.y, gv.z, gv.w};
        #pragma unroll
        for (int e = 0; e < 4; ++e) {
            if (ga[e] > thr) continue;
            const int code = (t * 4 + e) * 16 + code_off;
            const float* er = embed + (size_t)code * DIM + half * 128;
            float dot = 0.f;
            #pragma unroll
            for (int k = 0; k < 32; ++k) {
                float4 ev = *(const float4*)(er + k * 4);
                float4 xv = *(const float4*)(xh + k * 4);
                dot = fmaf(ev.x, xv.x, dot); dot = fmaf(ev.y, xv.y, dot);
                dot = fmaf(ev.z, xv.z, dot); dot = fmaf(ev.w, xv.w, dot);
            }
            dot += __shfl_xor_sync(0xffffffffu, dot, 1);
            float d = fmaf(-2.f, dot, g_esq[code]);
            unsigned long long key = mk_key(d, code);
            #pragma unroll
            for (int off = 2; off < 32; off <<= 1)
                key = umin64(key, __shfl_xor_sync(0xffffffffu, key, off));
            key = umin64(key, __shfl_xor_sync(0xffffffffu, key, 1));
            best = umin64(best, key);
        }
    }

    const int bidx = (int)(best & 0xffffffffull);
    #pragma unroll
    for (int t = lane; t < 64; t += 32) {
        float4 qv = *(const float4*)(embed + (size_t)bidx * DIM + t * 4);
        float4 xv = *(const float4*)(xs[w] + t * 4);
        float4 o;
        o.x = (qv.x - xv.x) + xv.x; o.y = (qv.y - xv.y) + xv.y;
        o.z = (qv.z - xv.z) + xv.z; o.w = (qv.w - xv.w) + xv.w;
        *(float4*)(out + (size_t)row * DIM + t * 4) = o;
    }
    if (lane == 0)
        out[(size_t)NROWS * DIM + row] = (float)bidx;
}

// ---------------------------------------------------------------------------
extern "C" void kernel_launch(void* const* d_in, const int* in_sizes, int n_in,
                              void* d_out, int out_size) {
    const float* x     = (const float*)d_in[0];   // [32768, 256]
    const float* embed = (const float*)d_in[1];   // [8192, 256]
    float*       out   = (float*)d_out;

    cudaFuncSetAttribute(vq_p1_kernel, cudaFuncAttributeMaxDynamicSharedMemorySize,
                         SMEM_TOTAL);

    conv_x_kernel<<<NROWS / 8, 256>>>(x);
    conv_e_kernel<<<NCODES / 8, 256>>>(embed);
    vq_p1_kernel<<<NROWS / BM, THREADS, SMEM_TOTAL>>>();
    vq_p2_kernel<<<NROWS / 8, 256>>>(x, embed, out);
}

// round 10
// speedup vs baseline: 4.1680x; 1.2326x over previous
#include <cuda_runtime.h>
#include <cuda_bf16.h>
#include <cstdint>

// ---------------------------------------------------------------------------
// VQ codebook assignment, N=32768 rows, K=8192 codes, D=256 (fp32).
// Phase 0: convert X,E to bf16 scratch; exact fp32 norms (e_sq, ||x||, max||e||).
// Phase 1: bf16 m16n8k16 mma.sync GEMM (ldmatrix-fed), per-8-code-group
//          approx-dist minima -> 128 MB scratch.
// Phase 2: per row, exact fp32 rescore of groups within a certified margin
//          (2x the provable bf16 distance error -> contains true argmin).
// R10 vs R9: 8-code groups (was 16), certified margin 0.0165 (was 0.033),
//            4-stage cp.async pipeline (was 3), leaner rescore (4 lanes/code).
// ---------------------------------------------------------------------------

#define NROWS   32768
#define NCODES  8192
#define DIM     256

#define BM      128                   // rows per CTA (phase 1)
#define BN      128                   // codes per chunk
#define NCHUNKS (NCODES / BN)         // 64
#define NKC     8                     // 32-dim stages per chunk
#define NSTG    4
#define THREADS 256
#define NGRP    (NCODES / 8)          // 1024 8-code groups

#define XPB     528                   // X smem row pitch bytes (264 bf16)
#define EPB     80                    // E smem row pitch bytes (40 bf16)
#define ESTG    (BM * EPB)            // 10240 per stage

#define SM_X    0
#define SM_E    (BM * XPB)                        // 67584
#define SM_ESQ  (SM_E + NSTG * ESTG)              // 108544
#define SMEM_TOTAL (SM_ESQ + 512 + 256)           // 109312

__device__ float          g_esq[NCODES];
__device__ float          g_xnorm[NROWS];
__device__ unsigned int   g_emax2b;               // max ||e||^2 (ordered bits)
__device__ __nv_bfloat16  g_xbf[(size_t)NROWS * DIM];    // 16 MB
__device__ __nv_bfloat16  g_ebf[(size_t)NCODES * DIM];   // 4 MB
__device__ float          g_gmin[(size_t)NROWS * NGRP];  // 128 MB

// ---------------- helpers ----------------
__device__ __forceinline__ uint32_t smem_u32(const void* p) {
    uint32_t a;
    asm("{ .reg .u64 t; cvta.to.shared.u64 t, %1; cvt.u32.u64 %0, t; }" : "=r"(a) : "l"(p));
    return a;
}
__device__ __forceinline__ uint32_t bf2(float lo, float hi) {   // pack (lo,hi)
    uint32_t r;
    asm("cvt.rn.bf16x2.f32 %0, %1, %2;" : "=r"(r) : "f"(hi), "f"(lo));
    return r;
}
__device__ __forceinline__ void mma_bf16(float* c, const uint32_t* a, const uint32_t* b) {
    asm volatile(
        "mma.sync.aligned.m16n8k16.row.col.f32.bf16.bf16.f32 "
        "{%0,%1,%2,%3}, {%4,%5,%6,%7}, {%8,%9}, {%0,%1,%2,%3};"
        : "+f"(c[0]), "+f"(c[1]), "+f"(c[2]), "+f"(c[3])
        : "r"(a[0]), "r"(a[1]), "r"(a[2]), "r"(a[3]), "r"(b[0]), "r"(b[1]));
}
__device__ __forceinline__ void ldsm_x4(uint32_t* r, uint32_t addr) {
    asm volatile("ldmatrix.sync.aligned.m8n8.x4.shared.b16 {%0,%1,%2,%3}, [%4];"
                 : "=r"(r[0]), "=r"(r[1]), "=r"(r[2]), "=r"(r[3]) : "r"(addr));
}
__device__ __forceinline__ unsigned long long mk_key(float v, int idx) {
    uint32_t u = __float_as_uint(v);
    u ^= (u & 0x80000000u) ? 0xFFFFFFFFu : 0x80000000u;
    return ((unsigned long long)u << 32) | (uint32_t)idx;
}
__device__ __forceinline__ unsigned long long umin64(unsigned long long a,
                                                     unsigned long long b) {
    return a < b ? a : b;
}

// one E stage: 128 codes x 32 dims bf16 (64 B/row) via cp.async
__device__ __forceinline__ void issue_stage(uint32_t sbase, int s, int tid) {
    const int chunk = s >> 3, kc = s & 7, buf = s & (NSTG - 1);
    const int r = tid >> 1, h = tid & 1;
    const __nv_bfloat16* src = g_ebf + (size_t)(chunk * BN + r) * DIM + kc * 32 + h * 16;
    uint32_t dst = sbase + SM_E + (uint32_t)(buf * ESTG + r * EPB + h * 32);
    asm volatile("cp.async.cg.shared.global [%0], [%1], 16;" :: "r"(dst),      "l"(src)     : "memory");
    asm volatile("cp.async.cg.shared.global [%0], [%1], 16;" :: "r"(dst + 16), "l"(src + 8) : "memory");
}

// ---------------------------------------------------------------------------
// Phase 0a: convert X -> bf16, ||x|| (one warp per row)
// ---------------------------------------------------------------------------
__global__ void conv_x_kernel(const float* __restrict__ x) {
    const int row  = blockIdx.x * 8 + (threadIdx.x >> 5);
    const int lane = threadIdx.x & 31;
    float s = 0.f;
    #pragma unroll
    for (int i = 0; i < 2; ++i) {
        const int off = i * 128 + lane * 4;
        float4 v = *(const float4*)(x + (size_t)row * DIM + off);
        s = fmaf(v.x, v.x, s); s = fmaf(v.y, v.y, s);
        s = fmaf(v.z, v.z, s); s = fmaf(v.w, v.w, s);
        uint2 p = make_uint2(bf2(v.x, v.y), bf2(v.z, v.w));
        *(uint2*)(g_xbf + (size_t)row * DIM + off) = p;
    }
    #pragma unroll
    for (int o = 16; o; o >>= 1) s += __shfl_xor_sync(0xffffffffu, s, o);
    if (lane == 0) g_xnorm[row] = sqrtf(s);
}

// ---------------------------------------------------------------------------
// Phase 0b: convert E -> bf16, e_sq, max ||e||^2 (one warp per row)
// ---------------------------------------------------------------------------
__global__ void conv_e_kernel(const float* __restrict__ embed) {
    const int row  = blockIdx.x * 8 + (threadIdx.x >> 5);
    const int lane = threadIdx.x & 31;
    float s = 0.f;
    #pragma unroll
    for (int i = 0; i < 2; ++i) {
        const int off = i * 128 + lane * 4;
        float4 v = *(const float4*)(embed + (size_t)row * DIM + off);
        s = fmaf(v.x, v.x, s); s = fmaf(v.y, v.y, s);
        s = fmaf(v.z, v.z, s); s = fmaf(v.w, v.w, s);
        uint2 p = make_uint2(bf2(v.x, v.y), bf2(v.z, v.w));
        *(uint2*)(g_ebf + (size_t)row * DIM + off) = p;
    }
    #pragma unroll
    for (int o = 16; o; o >>= 1) s += __shfl_xor_sync(0xffffffffu, s, o);
    if (lane == 0) {
        g_esq[row] = s;
        atomicMax(&g_emax2b, __float_as_uint(s));   // positive: bit order = value order
    }
}

// ---------------------------------------------------------------------------
// Phase 1: bf16 GEMM + per-8-code-group approx-dist minima
// ---------------------------------------------------------------------------
__global__ void __launch_bounds__(THREADS, 2)
vq_p1_kernel(void) {
    extern __shared__ char smem[];
    float* esq_s = (float*)(smem + SM_ESQ);
    const uint32_t sbase = smem_u32(smem);

    const int tid  = threadIdx.x;
    const int lane = tid & 31;
    const int wid  = tid >> 5;
    const int wm   = wid & 1;                 // 64-row half
    const int wn   = wid >> 1;                // 32-code quarter
    const int gq   = lane >> 2;
    const int q    = lane & 3;
    const int row0 = blockIdx.x * BM;

    issue_stage(sbase, 0, tid);
    asm volatile("cp.async.commit_group;" ::: "memory");
    issue_stage(sbase, 1, tid);
    asm volatile("cp.async.commit_group;" ::: "memory");
    issue_stage(sbase, 2, tid);
    asm volatile("cp.async.commit_group;" ::: "memory");

    // X tile: 128 rows x 256 bf16, pitch 528 B (LDSM conflict-free)
    #pragma unroll
    for (int i = 0; i < 16; ++i) {
        int idx = tid + i * THREADS;          // 0..4095 16B chunks
        int r = idx >> 5, o = idx & 31;
        *(uint4*)(smem + SM_X + r * XPB + o * 16) =
            *(const uint4*)(g_xbf + (size_t)(row0 + r) * DIM + o * 8);
    }

    // ldmatrix lane->address mapping (x4 = four 8x8 matrices)
    const int t = lane >> 3;
    const uint32_t a_rowsel = (uint32_t)((t & 1) * 8 + (lane & 7));
    const uint32_t a_koff   = (uint32_t)((t >> 1) * 16);             // bytes
    uint32_t abase[4];
    #pragma unroll
    for (int f = 0; f < 4; ++f)
        abase[f] = sbase + SM_X + (wm * 64 + f * 16 + a_rowsel) * XPB + a_koff;
    const uint32_t b_nsel = (uint32_t)(((lane >> 4) & 1) * 8 + (lane & 7));
    const uint32_t b_koff = (uint32_t)(((lane >> 3) & 1) * 16);      // bytes
    uint32_t bbase[2];
    #pragma unroll
    for (int jp = 0; jp < 2; ++jp)
        bbase[jp] = sbase + SM_E + (wn * 32 + jp * 16 + b_nsel) * EPB + b_koff;

    #pragma unroll 1
    for (int c = 0; c < NCHUNKS; ++c) {
        float acc[4][4][4];
        #pragma unroll
        for (int f = 0; f < 4; ++f)
            #pragma unroll
            for (int j = 0; j < 4; ++j)
                #pragma unroll
                for (int r = 0; r < 4; ++r) acc[f][j][r] = 0.f;

        #pragma unroll 1
        for (int kc = 0; kc < NKC; ++kc) {
            asm volatile("cp.async.wait_group 2;" ::: "memory");
            __syncthreads();
            if (kc == 0 && tid < BN) esq_s[tid] = g_esq[c * BN + tid];

            const int g = c * NKC + kc;
            const uint32_t ebuf = (uint32_t)((g & (NSTG - 1)) * ESTG);

            #pragma unroll
            for (int s = 0; s < 2; ++s) {     // two k16 steps per 32-dim stage
                const uint32_t ak = (uint32_t)((kc * 32 + s * 16) * 2);
                const uint32_t bk = (uint32_t)(s * 32);
                uint32_t a[4][4], b[4][2];
                #pragma unroll
                for (int f = 0; f < 4; ++f) ldsm_x4(a[f], abase[f] + ak);
                #pragma unroll
                for (int jp = 0; jp < 2; ++jp) {
                    uint32_t rr[4];
                    ldsm_x4(rr, bbase[jp] + ebuf + bk);          // non-trans
                    b[jp * 2][0]     = rr[0];  // (n0-7, k0-7)
                    b[jp * 2][1]     = rr[1];  // (n0-7, k8-15)
                    b[jp * 2 + 1][0] = rr[2];  // (n8-15, k0-7)
                    b[jp * 2 + 1][1] = rr[3];  // (n8-15, k8-15)
                }
                #pragma unroll
                for (int f = 0; f < 4; ++f)
                    #pragma unroll
                    for (int j = 0; j < 4; ++j)
                        mma_bf16(acc[f][j], a[f], b[j]);
            }

            if (g + 3 < NCHUNKS * NKC) issue_stage(sbase, g + 3, tid);
            asm volatile("cp.async.commit_group;" ::: "memory");
        }

        // ---- per-row minima of the 4 8-code groups this warp covers
        #pragma unroll
        for (int f = 0; f < 4; ++f) {
            #pragma unroll
            for (int h = 0; h < 2; ++h) {
                float m[4];
                #pragma unroll
                for (int j = 0; j < 4; ++j) {
                    const int nloc = wn * 32 + j * 8 + 2 * q;
                    const float2 e2 = *(const float2*)(esq_s + nloc);
                    float d0 = fmaf(-2.f, acc[f][j][2 * h + 0], e2.x);
                    float d1 = fmaf(-2.f, acc[f][j][2 * h + 1], e2.y);
                    float mm = fminf(d0, d1);
                    mm = fminf(mm, __shfl_xor_sync(0xffffffffu, mm, 1));
                    mm = fminf(mm, __shfl_xor_sync(0xffffffffu, mm, 2));
                    m[j] = mm;
                }
                if (q == 0) {
                    const int row = row0 + wm * 64 + f * 16 + h * 8 + gq;
                    *(float4*)(g_gmin + (size_t)row * NGRP + c * 16 + wn * 4) =
                        make_float4(m[0], m[1], m[2], m[3]);
                }
            }
        }
    }
}

// ---------------------------------------------------------------------------
// Phase 2: exact fp32 rescore of candidate groups + gather (1 warp/row)
// ---------------------------------------------------------------------------
__global__ void __launch_bounds__(256)
vq_p2_kernel(const float* __restrict__ x,
             const float* __restrict__ embed,
             float* __restrict__ out) {
    __shared__ float xs[8][DIM];          // 8 KB
    __shared__ float gm[8][NGRP];         // 32 KB

    const int lane = threadIdx.x & 31;
    const int w    = threadIdx.x >> 5;
    const int row  = blockIdx.x * 8 + w;

    #pragma unroll
    for (int t = lane; t < 64; t += 32)
        *(float4*)(xs[w] + t * 4) = *(const float4*)(x + (size_t)row * DIM + t * 4);

    float mn = __int_as_float(0x7f800000);
    const float* gsrc = g_gmin + (size_t)row * NGRP;
    #pragma unroll
    for (int t = lane; t < NGRP / 4; t += 32) {
        float4 v = *(const float4*)(gsrc + t * 4);
        *(float4*)(gm[w] + t * 4) = v;
        mn = fminf(mn, fminf(fminf(v.x, v.y), fminf(v.z, v.w)));
    }
    #pragma unroll
    for (int off = 16; off; off >>= 1)
        mn = fminf(mn, __shfl_xor_sync(0xffffffffu, mn, off));

    // certified: |dist err| <= 2*(2^-9+2^-9)*||x||*||e||max ~= 0.0079*||x||*emax
    // two-sided argmin containment needs 2x -> 0.0165 coefficient (+ slack)
    const float emax = sqrtf(__uint_as_float(g_emax2b));
    const float thr  = mn + fmaf(0.0165f, g_xnorm[row] * emax, 0.1f);
    __syncwarp();

    unsigned long long best = ~0ull;
    const int code_off = lane >> 2;        // 8 codes, 4 lanes each
    const int quar     = lane & 3;         // 64-dim quarter per lane
    const float* xq = xs[w] + quar * 64;

    #pragma unroll 1
    for (int t = 0; t < NGRP / 4; ++t) {
        float4 gv = *(const float4*)(gm[w] + t * 4);
        float m4 = fminf(fminf(gv.x, gv.y), fminf(gv.z, gv.w));
        if (m4 > thr) continue;
        float ga[4] = {gv.x, gv.y, gv.z, gv.w};
        #pragma unroll
        for (int e = 0; e < 4; ++e) {
            if (ga[e] > thr) continue;
            const int code = (t * 4 + e) * 8 + code_off;
            const float* er = embed + (size_t)code * DIM + quar * 64;
            float dot = 0.f;
            #pragma unroll
            for (int k = 0; k < 16; ++k) {
                float4 ev = *(const float4*)(er + k * 4);
                float4 xv = *(const float4*)(xq + k * 4);
                dot = fmaf(ev.x, xv.x, dot); dot = fmaf(ev.y, xv.y, dot);
                dot = fmaf(ev.z, xv.z, dot); dot = fmaf(ev.w, xv.w, dot);
            }
            dot += __shfl_xor_sync(0xffffffffu, dot, 1);   // combine quarters
            dot += __shfl_xor_sync(0xffffffffu, dot, 2);
            float d = fmaf(-2.f, dot, g_esq[code]);
            unsigned long long key = mk_key(d, code);
            key = umin64(key, __shfl_xor_sync(0xffffffffu, key, 4));
            key = umin64(key, __shfl_xor_sync(0xffffffffu, key, 8));
            key = umin64(key, __shfl_xor_sync(0xffffffffu, key, 16));
            best = umin64(best, key);
        }
    }

    const int bidx = (int)(best & 0xffffffffull);
    #pragma unroll
    for (int t = lane; t < 64; t += 32) {
        float4 qv = *(const float4*)(embed + (size_t)bidx * DIM + t * 4);
        float4 xv = *(const float4*)(xs[w] + t * 4);
        float4 o;
        o.x = (qv.x - xv.x) + xv.x; o.y = (qv.y - xv.y) + xv.y;
        o.z = (qv.z - xv.z) + xv.z; o.w = (qv.w - xv.w) + xv.w;
        *(float4*)(out + (size_t)row * DIM + t * 4) = o;
    }
    if (lane == 0)
        out[(size_t)NROWS * DIM + row] = (float)bidx;
}

// ---------------------------------------------------------------------------
extern "C" void kernel_launch(void* const* d_in, const int* in_sizes, int n_in,
                              void* d_out, int out_size) {
    const float* x     = (const float*)d_in[0];   // [32768, 256]
    const float* embed = (const float*)d_in[1];   // [8192, 256]
    float*       out   = (float*)d_out;

    cudaFuncSetAttribute(vq_p1_kernel, cudaFuncAttributeMaxDynamicSharedMemorySize,
                         SMEM_TOTAL);

    conv_x_kernel<<<NROWS / 8, 256>>>(x);
    conv_e_kernel<<<NCODES / 8, 256>>>(embed);
    vq_p1_kernel<<<NROWS / BM, THREADS, SMEM_TOTAL>>>();
    vq_p2_kernel<<<NROWS / 8, 256>>>(x, embed, out);
}

// round 11
// speedup vs baseline: 5.0191x; 1.2042x over previous
#include <cuda_runtime.h>
#include <cuda_bf16.h>
#include <cstdint>

// ---------------------------------------------------------------------------
// VQ codebook assignment, N=32768 rows, K=8192 codes, D=256 (fp32).
// Phase 0: convert E to bf16 scratch; exact fp32 e_sq + max||e||.
// Phase 1: bf16 m16n8k16 mma.sync GEMM (ldmatrix-fed, X converted inline),
//          per-8-code-group approx-dist minima -> 128 MB scratch.
// Phase 2: ballot-compacted candidate scan + exact fp32 rescore within a
//          certified margin (contains true argmin), fused gather.
// R11 vs R10: register scan + ballot compaction in p2 (kills the 83%-ALU
// uniform scan), conv_x folded into p1 (inline cvt) and p2 (||x|| on the fly).
// ---------------------------------------------------------------------------

#define NROWS   32768
#define NCODES  8192
#define DIM     256

#define BM      128                   // rows per CTA (phase 1)
#define BN      128                   // codes per chunk
#define NCHUNKS (NCODES / BN)         // 64
#define NKC     8                     // 32-dim stages per chunk
#define NSTG    4
#define THREADS 256
#define NGRP    (NCODES / 8)          // 1024 8-code groups

#define XPB     528                   // X smem row pitch bytes (264 bf16)
#define EPB     80                    // E smem row pitch bytes (40 bf16)
#define ESTG    (BM * EPB)            // 10240 per stage

#define SM_X    0
#define SM_E    (BM * XPB)                        // 67584
#define SM_ESQ  (SM_E + NSTG * ESTG)              // 108544
#define SMEM_TOTAL (SM_ESQ + 512 + 256)           // 109312

__device__ float          g_esq[NCODES];
__device__ unsigned int   g_emax2b;               // max ||e||^2 (ordered bits)
__device__ __nv_bfloat16  g_ebf[(size_t)NCODES * DIM];   // 4 MB
__device__ float          g_gmin[(size_t)NROWS * NGRP];  // 128 MB

// ---------------- helpers ----------------
__device__ __forceinline__ uint32_t smem_u32(const void* p) {
    uint32_t a;
    asm("{ .reg .u64 t; cvta.to.shared.u64 t, %1; cvt.u32.u64 %0, t; }" : "=r"(a) : "l"(p));
    return a;
}
__device__ __forceinline__ uint32_t bf2(float lo, float hi) {   // pack (lo,hi)
    uint32_t r;
    asm("cvt.rn.bf16x2.f32 %0, %1, %2;" : "=r"(r) : "f"(hi), "f"(lo));
    return r;
}
__device__ __forceinline__ void mma_bf16(float* c, const uint32_t* a, const uint32_t* b) {
    asm volatile(
        "mma.sync.aligned.m16n8k16.row.col.f32.bf16.bf16.f32 "
        "{%0,%1,%2,%3}, {%4,%5,%6,%7}, {%8,%9}, {%0,%1,%2,%3};"
        : "+f"(c[0]), "+f"(c[1]), "+f"(c[2]), "+f"(c[3])
        : "r"(a[0]), "r"(a[1]), "r"(a[2]), "r"(a[3]), "r"(b[0]), "r"(b[1]));
}
__device__ __forceinline__ void ldsm_x4(uint32_t* r, uint32_t addr) {
    asm volatile("ldmatrix.sync.aligned.m8n8.x4.shared.b16 {%0,%1,%2,%3}, [%4];"
                 : "=r"(r[0]), "=r"(r[1]), "=r"(r[2]), "=r"(r[3]) : "r"(addr));
}
__device__ __forceinline__ unsigned long long mk_key(float v, int idx) {
    uint32_t u = __float_as_uint(v);
    u ^= (u & 0x80000000u) ? 0xFFFFFFFFu : 0x80000000u;
    return ((unsigned long long)u << 32) | (uint32_t)idx;
}
__device__ __forceinline__ unsigned long long umin64(unsigned long long a,
                                                     unsigned long long b) {
    return a < b ? a : b;
}

// one E stage: 128 codes x 32 dims bf16 (64 B/row) via cp.async
__device__ __forceinline__ void issue_stage(uint32_t sbase, int s, int tid) {
    const int chunk = s >> 3, kc = s & 7, buf = s & (NSTG - 1);
    const int r = tid >> 1, h = tid & 1;
    const __nv_bfloat16* src = g_ebf + (size_t)(chunk * BN + r) * DIM + kc * 32 + h * 16;
    uint32_t dst = sbase + SM_E + (uint32_t)(buf * ESTG + r * EPB + h * 32);
    asm volatile("cp.async.cg.shared.global [%0], [%1], 16;" :: "r"(dst),      "l"(src)     : "memory");
    asm volatile("cp.async.cg.shared.global [%0], [%1], 16;" :: "r"(dst + 16), "l"(src + 8) : "memory");
}

// ---------------------------------------------------------------------------
// Phase 0: convert E -> bf16, e_sq, max ||e||^2 (one warp per row)
// ---------------------------------------------------------------------------
__global__ void conv_e_kernel(const float* __restrict__ embed) {
    const int row  = blockIdx.x * 8 + (threadIdx.x >> 5);
    const int lane = threadIdx.x & 31;
    float s = 0.f;
    #pragma unroll
    for (int i = 0; i < 2; ++i) {
        const int off = i * 128 + lane * 4;
        float4 v = *(const float4*)(embed + (size_t)row * DIM + off);
        s = fmaf(v.x, v.x, s); s = fmaf(v.y, v.y, s);
        s = fmaf(v.z, v.z, s); s = fmaf(v.w, v.w, s);
        uint2 p = make_uint2(bf2(v.x, v.y), bf2(v.z, v.w));
        *(uint2*)(g_ebf + (size_t)row * DIM + off) = p;
    }
    #pragma unroll
    for (int o = 16; o; o >>= 1) s += __shfl_xor_sync(0xffffffffu, s, o);
    if (lane == 0) {
        g_esq[row] = s;
        atomicMax(&g_emax2b, __float_as_uint(s));   // positive: bit order = value order
    }
}

// ---------------------------------------------------------------------------
// Phase 1: bf16 GEMM + per-8-code-group approx-dist minima
// ---------------------------------------------------------------------------
__global__ void __launch_bounds__(THREADS, 2)
vq_p1_kernel(const float* __restrict__ x) {
    extern __shared__ char smem[];
    float* esq_s = (float*)(smem + SM_ESQ);
    const uint32_t sbase = smem_u32(smem);

    const int tid  = threadIdx.x;
    const int lane = tid & 31;
    const int wid  = tid >> 5;
    const int wm   = wid & 1;                 // 64-row half
    const int wn   = wid >> 1;                // 32-code quarter
    const int gq   = lane >> 2;
    const int q    = lane & 3;
    const int row0 = blockIdx.x * BM;

    issue_stage(sbase, 0, tid);
    asm volatile("cp.async.commit_group;" ::: "memory");
    issue_stage(sbase, 1, tid);
    asm volatile("cp.async.commit_group;" ::: "memory");
    issue_stage(sbase, 2, tid);
    asm volatile("cp.async.commit_group;" ::: "memory");

    // X tile: load fp32, convert inline to bf16, pitch 528 B (LDSM clean)
    #pragma unroll
    for (int i = 0; i < 32; ++i) {
        int idx = tid + i * THREADS;          // 0..8191 float4 chunks
        int r = idx >> 6, c4 = (idx & 63) << 2;
        float4 v = *(const float4*)(x + (size_t)(row0 + r) * DIM + c4);
        uint2 p = make_uint2(bf2(v.x, v.y), bf2(v.z, v.w));
        *(uint2*)(smem + SM_X + r * XPB + c4 * 2) = p;
    }

    // ldmatrix lane->address mapping (x4 = four 8x8 matrices)
    const int t = lane >> 3;
    const uint32_t a_rowsel = (uint32_t)((t & 1) * 8 + (lane & 7));
    const uint32_t a_koff   = (uint32_t)((t >> 1) * 16);             // bytes
    uint32_t abase[4];
    #pragma unroll
    for (int f = 0; f < 4; ++f)
        abase[f] = sbase + SM_X + (wm * 64 + f * 16 + a_rowsel) * XPB + a_koff;
    const uint32_t b_nsel = (uint32_t)(((lane >> 4) & 1) * 8 + (lane & 7));
    const uint32_t b_koff = (uint32_t)(((lane >> 3) & 1) * 16);      // bytes
    uint32_t bbase[2];
    #pragma unroll
    for (int jp = 0; jp < 2; ++jp)
        bbase[jp] = sbase + SM_E + (wn * 32 + jp * 16 + b_nsel) * EPB + b_koff;

    #pragma unroll 1
    for (int c = 0; c < NCHUNKS; ++c) {
        float acc[4][4][4];
        #pragma unroll
        for (int f = 0; f < 4; ++f)
            #pragma unroll
            for (int j = 0; j < 4; ++j)
                #pragma unroll
                for (int r = 0; r < 4; ++r) acc[f][j][r] = 0.f;

        #pragma unroll 1
        for (int kc = 0; kc < NKC; ++kc) {
            asm volatile("cp.async.wait_group 2;" ::: "memory");
            __syncthreads();
            if (kc == 0 && tid < BN) esq_s[tid] = g_esq[c * BN + tid];

            const int g = c * NKC + kc;
            const uint32_t ebuf = (uint32_t)((g & (NSTG - 1)) * ESTG);

            #pragma unroll
            for (int s = 0; s < 2; ++s) {     // two k16 steps per 32-dim stage
                const uint32_t ak = (uint32_t)((kc * 32 + s * 16) * 2);
                const uint32_t bk = (uint32_t)(s * 32);
                uint32_t a[4][4], b[4][2];
                #pragma unroll
                for (int f = 0; f < 4; ++f) ldsm_x4(a[f], abase[f] + ak);
                #pragma unroll
                for (int jp = 0; jp < 2; ++jp) {
                    uint32_t rr[4];
                    ldsm_x4(rr, bbase[jp] + ebuf + bk);          // non-trans
                    b[jp * 2][0]     = rr[0];
                    b[jp * 2][1]     = rr[1];
                    b[jp * 2 + 1][0] = rr[2];
                    b[jp * 2 + 1][1] = rr[3];
                }
                #pragma unroll
                for (int f = 0; f < 4; ++f)
                    #pragma unroll
                    for (int j = 0; j < 4; ++j)
                        mma_bf16(acc[f][j], a[f], b[j]);
            }

            if (g + 3 < NCHUNKS * NKC) issue_stage(sbase, g + 3, tid);
            asm volatile("cp.async.commit_group;" ::: "memory");
        }

        // ---- per-row minima of the 4 8-code groups this warp covers
        #pragma unroll
        for (int f = 0; f < 4; ++f) {
            #pragma unroll
            for (int h = 0; h < 2; ++h) {
                float m[4];
                #pragma unroll
                for (int j = 0; j < 4; ++j) {
                    const int nloc = wn * 32 + j * 8 + 2 * q;
                    const float2 e2 = *(const float2*)(esq_s + nloc);
                    float d0 = fmaf(-2.f, acc[f][j][2 * h + 0], e2.x);
                    float d1 = fmaf(-2.f, acc[f][j][2 * h + 1], e2.y);
                    float mm = fminf(d0, d1);
                    mm = fminf(mm, __shfl_xor_sync(0xffffffffu, mm, 1));
                    mm = fminf(mm, __shfl_xor_sync(0xffffffffu, mm, 2));
                    m[j] = mm;
                }
                if (q == 0) {
                    const int row = row0 + wm * 64 + f * 16 + h * 8 + gq;
                    *(float4*)(g_gmin + (size_t)row * NGRP + c * 16 + wn * 4) =
                        make_float4(m[0], m[1], m[2], m[3]);
                }
            }
        }
    }
}

// ---------------------------------------------------------------------------
// Phase 2: ballot-compacted candidate scan + exact rescore + gather
// (1 warp per row; 8 warps per block)
// ---------------------------------------------------------------------------
__global__ void __launch_bounds__(256)
vq_p2_kernel(const float* __restrict__ x,
             const float* __restrict__ embed,
             float* __restrict__ out) {
    __shared__ float xs[8][DIM];          // 8 KB
    __shared__ short cand[8][NGRP];       // 16 KB (overflow impossible)

    const int lane = threadIdx.x & 31;
    const int w    = threadIdx.x >> 5;
    const int row  = blockIdx.x * 8 + w;

    // x row -> smem, ||x||^2 on the fly
    float xn2 = 0.f;
    #pragma unroll
    for (int t = lane; t < 64; t += 32) {
        float4 v = *(const float4*)(x + (size_t)row * DIM + t * 4);
        *(float4*)(xs[w] + t * 4) = v;
        xn2 = fmaf(v.x, v.x, xn2); xn2 = fmaf(v.y, v.y, xn2);
        xn2 = fmaf(v.z, v.z, xn2); xn2 = fmaf(v.w, v.w, xn2);
    }
    #pragma unroll
    for (int o = 16; o; o >>= 1) xn2 += __shfl_xor_sync(0xffffffffu, xn2, o);

    // group minima -> registers (lane i holds groups 4*(lane+32i)+e)
    float4 v[8];
    float mn = __int_as_float(0x7f800000);
    const float4* gsrc = (const float4*)(g_gmin + (size_t)row * NGRP);
    #pragma unroll
    for (int i = 0; i < 8; ++i) {
        v[i] = gsrc[lane + 32 * i];
        mn = fminf(mn, fminf(fminf(v[i].x, v[i].y), fminf(v[i].z, v[i].w)));
    }
    #pragma unroll
    for (int off = 16; off; off >>= 1)
        mn = fminf(mn, __shfl_xor_sync(0xffffffffu, mn, off));

    // certified: |dist err| <= 2*(2^-9+2^-9)*||x||*||e||max; 2x for containment
    const float emax = sqrtf(__uint_as_float(g_emax2b));
    const float thr  = mn + fmaf(0.0165f, sqrtf(xn2) * emax, 0.1f);

    // ballot compaction: 32 rounds, ~8 instr each
    int ncand = 0;
    #pragma unroll
    for (int i = 0; i < 8; ++i) {
        const float ge[4] = {v[i].x, v[i].y, v[i].z, v[i].w};
        #pragma unroll
        for (int e = 0; e < 4; ++e) {
            const bool c = (ge[e] <= thr);
            const uint32_t m = __ballot_sync(0xffffffffu, c);
            if (c) {
                const int pos = ncand + __popc(m & ((1u << lane) - 1u));
                cand[w][pos] = (short)(4 * (lane + 32 * i) + e);
            }
            ncand += __popc(m);
        }
    }
    __syncwarp();

    // rescore candidates exactly (8 codes/group, 4 lanes/code, 64 dims/lane)
    unsigned long long best = ~0ull;
    const int code_off = lane >> 2;
    const int quar     = lane & 3;
    const float* xq = xs[w] + quar * 64;

    #pragma unroll 1
    for (int ci = 0; ci < ncand; ++ci) {
        const int grp  = cand[w][ci];
        const int code = grp * 8 + code_off;
        const float* er = embed + (size_t)code * DIM + quar * 64;
        float dot = 0.f;
        #pragma unroll
        for (int k = 0; k < 16; ++k) {
            float4 ev = *(const float4*)(er + k * 4);
            float4 xv = *(const float4*)(xq + k * 4);
            dot = fmaf(ev.x, xv.x, dot); dot = fmaf(ev.y, xv.y, dot);
            dot = fmaf(ev.z, xv.z, dot); dot = fmaf(ev.w, xv.w, dot);
        }
        dot += __shfl_xor_sync(0xffffffffu, dot, 1);   // combine quarters
        dot += __shfl_xor_sync(0xffffffffu, dot, 2);
        float d = fmaf(-2.f, dot, g_esq[code]);
        unsigned long long key = mk_key(d, code);
        key = umin64(key, __shfl_xor_sync(0xffffffffu, key, 4));
        key = umin64(key, __shfl_xor_sync(0xffffffffu, key, 8));
        key = umin64(key, __shfl_xor_sync(0xffffffffu, key, 16));
        best = umin64(best, key);
    }

    const int bidx = (int)(best & 0xffffffffull);
    #pragma unroll
    for (int t = lane; t < 64; t += 32) {
        float4 qv = *(const float4*)(embed + (size_t)bidx * DIM + t * 4);
        float4 xv = *(const float4*)(xs[w] + t * 4);
        float4 o;
        o.x = (qv.x - xv.x) + xv.x; o.y = (qv.y - xv.y) + xv.y;
        o.z = (qv.z - xv.z) + xv.z; o.w = (qv.w - xv.w) + xv.w;
        *(float4*)(out + (size_t)row * DIM + t * 4) = o;
    }
    if (lane == 0)
        out[(size_t)NROWS * DIM + row] = (float)bidx;
}

// ---------------------------------------------------------------------------
extern "C" void kernel_launch(void* const* d_in, const int* in_sizes, int n_in,
                              void* d_out, int out_size) {
    const float* x     = (const float*)d_in[0];   // [32768, 256]
    const float* embed = (const float*)d_in[1];   // [8192, 256]
    float*       out   = (float*)d_out;

    cudaFuncSetAttribute(vq_p1_kernel, cudaFuncAttributeMaxDynamicSharedMemorySize,
                         SMEM_TOTAL);

    conv_e_kernel<<<NCODES / 8, 256>>>(embed);
    vq_p1_kernel<<<NROWS / BM, THREADS, SMEM_TOTAL>>>(x);
    vq_p2_kernel<<<NROWS / 8, 256>>>(x, embed, out);
}